// round 4
// baseline (speedup 1.0000x reference)
#include <cuda_runtime.h>
#include <cuda_bf16.h>
#include <math.h>

// Problem constants
#define B_    2
#define L_    2048
#define D_    2048
#define H_    16
#define KVH_  4
#define DK_   128
#define DKV_  512            // KVH_ * DK_
#define M_    (B_ * L_)      // 4096 rows
#define CAPV  50.0f

// ---------------- scratch (static device globals; no allocation) ----------------
static __device__ float g_Q[(size_t)M_ * D_];
static __device__ float g_K[(size_t)M_ * DKV_];
static __device__ float g_V[(size_t)M_ * DKV_];
static __device__ float g_O[(size_t)M_ * D_];
static __device__ float g_cos[L_ * 64];
static __device__ float g_sin[L_ * 64];

// ---------------- RoPE table ----------------
__global__ void rope_table_kernel() {
    int idx = blockIdx.x * blockDim.x + threadIdx.x;
    if (idx >= L_ * 64) return;
    int pos = idx >> 6;
    int i   = idx & 63;
    float expnt = (float)(2 * i) / 128.0f;
    float invf  = powf(10000.0f, -expnt);
    float f     = (float)pos * invf;
    g_cos[idx] = cosf(f);
    g_sin[idx] = sinf(f);
}

// ---------------- RoPE apply + clip (in place) ----------------
__global__ void rope_apply_kernel(float* __restrict__ X, int heads, int rowstride) {
    int idx   = blockIdx.x * blockDim.x + threadIdx.x;
    int total = M_ * heads * 64;
    if (idx >= total) return;
    int i   = idx & 63;
    int t   = idx >> 6;
    int h   = t % heads;
    int row = t / heads;
    int pos = row & (L_ - 1);
    float c = g_cos[(pos << 6) + i];
    float s = g_sin[(pos << 6) + i];
    float* p = X + (size_t)row * rowstride + h * DK_ + i;
    float x1 = p[0], x2 = p[64];
    float o1 = x1 * c - x2 * s;
    float o2 = x1 * s + x2 * c;
    p[0]  = fminf(fmaxf(o1, -CAPV), CAPV);
    p[64] = fminf(fmaxf(o2, -CAPV), CAPV);
}

// ---------------- tf32 helpers ----------------
__device__ __forceinline__ float to_tf32(float x) {
    float r;
    asm("cvt.rna.tf32.f32 %0, %1;" : "=f"(r) : "f"(x));
    return r;
}

__device__ __forceinline__ void mma_tf32(float* c, const float4& a, const float2& b) {
    const unsigned* A  = reinterpret_cast<const unsigned*>(&a);
    const unsigned* Bv = reinterpret_cast<const unsigned*>(&b);
    asm volatile(
        "mma.sync.aligned.m16n8k8.row.col.f32.tf32.tf32.f32 "
        "{%0,%1,%2,%3}, {%4,%5,%6,%7}, {%8,%9}, {%0,%1,%2,%3};"
        : "+f"(c[0]), "+f"(c[1]), "+f"(c[2]), "+f"(c[3])
        : "r"(A[0]), "r"(A[1]), "r"(A[2]), "r"(A[3]), "r"(Bv[0]), "r"(Bv[1]));
}

// ---------------- tf32 NT GEMM, double-buffered ----------------
// C[M,N] = A[M,K] * Bw[N,K]^T.  BM=BN=128, BK=32, 256 threads (8 warps 2x4).
// smem stages hold fragment-permuted tf32 tiles (single LDS.128/LDS.64 per frag).
#define GEMM_SMEM_BYTES (2 * (16384 + 16384))

__global__ void __launch_bounds__(256) gemm_tf32_kernel(
    const float* __restrict__ A, const float* __restrict__ Bw,
    float* __restrict__ C, int M, int N, int K)
{
    extern __shared__ float4 smem_g[];
    float4* sA = smem_g;                       // [2][1024] float4
    float2* sB = (float2*)(smem_g + 2048);     // [2][2048] float2

    const int tid    = threadIdx.x;
    const int lane   = tid & 31;
    const int wid    = tid >> 5;
    const int warp_m = wid & 1;
    const int warp_n = wid >> 1;
    const int bm     = blockIdx.y << 7;
    const int bn     = blockIdx.x << 7;

    float acc[4][4][4];
    #pragma unroll
    for (int mt = 0; mt < 4; mt++)
        #pragma unroll
        for (int nt = 0; nt < 4; nt++)
            #pragma unroll
            for (int r = 0; r < 4; r++) acc[mt][nt][r] = 0.0f;

    float4 avA[4], avB[4];
    #pragma unroll
    for (int i = 0; i < 4; i++) {
        int idx = tid + (i << 8);
        int row = idx >> 3;
        int c4  = idx & 7;
        avA[i] = *(const float4*)(A  + (size_t)(bm + row) * K + (c4 << 2));
        avB[i] = *(const float4*)(Bw + (size_t)(bn + row) * K + (c4 << 2));
    }

    auto store_stage = [&](int s) {
        float4* dA = sA + s * 1024;
        float2* dB = sB + s * 2048;
        #pragma unroll
        for (int i = 0; i < 4; i++) {
            int idx = tid + (i << 8);
            int row = idx >> 3;
            int c4  = idx & 7;
            int ks   = c4 >> 1;
            int half = c4 & 1;
            {
                int mq = row >> 4;
                int rr = row & 15;
                int g  = rr & 7;
                int hi = rr >> 3;
                float* dst = (float*)&dA[((mq * 4 + ks) << 5) + (g << 2)] + (half << 1) + hi;
                float4 v = avA[i];
                dst[0]  = to_tf32(v.x);
                dst[4]  = to_tf32(v.y);
                dst[8]  = to_tf32(v.z);
                dst[12] = to_tf32(v.w);
            }
            {
                int nq = row >> 3;
                int g  = row & 7;
                float* dst = (float*)&dB[((nq * 4 + ks) << 5) + (g << 2)] + half;
                float4 v = avB[i];
                dst[0] = to_tf32(v.x);
                dst[2] = to_tf32(v.y);
                dst[4] = to_tf32(v.z);
                dst[6] = to_tf32(v.w);
            }
        }
    };

    store_stage(0);
    __syncthreads();

    const int stages = K >> 5;
    for (int kt = 0; kt < stages; kt++) {
        const int s = kt & 1;
        const bool has_next = (kt + 1) < stages;
        if (has_next) {
            int koff = (kt + 1) << 5;
            #pragma unroll
            for (int i = 0; i < 4; i++) {
                int idx = tid + (i << 8);
                int row = idx >> 3;
                int c4  = idx & 7;
                avA[i] = *(const float4*)(A  + (size_t)(bm + row) * K + koff + (c4 << 2));
                avB[i] = *(const float4*)(Bw + (size_t)(bn + row) * K + koff + (c4 << 2));
            }
        }

        const float4* rA = sA + s * 1024;
        const float2* rB = sB + s * 2048;
        #pragma unroll
        for (int ks = 0; ks < 4; ks++) {
            float4 a[4];
            float2 b[4];
            #pragma unroll
            for (int mt = 0; mt < 4; mt++)
                a[mt] = rA[(((warp_m * 4 + mt) * 4 + ks) << 5) + lane];
            #pragma unroll
            for (int nt = 0; nt < 4; nt++)
                b[nt] = rB[(((warp_n * 4 + nt) * 4 + ks) << 5) + lane];
            #pragma unroll
            for (int mt = 0; mt < 4; mt++)
                #pragma unroll
                for (int nt = 0; nt < 4; nt++)
                    mma_tf32(acc[mt][nt], a[mt], b[nt]);
        }

        if (has_next) store_stage(s ^ 1);
        __syncthreads();
    }

    const int g   = lane >> 2;
    const int tig = lane & 3;
    #pragma unroll
    for (int mt = 0; mt < 4; mt++) {
        int r0 = bm + warp_m * 64 + mt * 16 + g;
        #pragma unroll
        for (int nt = 0; nt < 4; nt++) {
            int c = bn + warp_n * 32 + nt * 8 + (tig << 1);
            *(float2*)(&C[(size_t)r0 * N + c])       = make_float2(acc[mt][nt][0], acc[mt][nt][1]);
            *(float2*)(&C[(size_t)(r0 + 8) * N + c]) = make_float2(acc[mt][nt][2], acc[mt][nt][3]);
        }
    }
}

// ---------------- tf32 tensor-core flash attention (causal) ----------------
// CTA: 64 q-rows x 64 kv tile, DK=128. 256 threads, 8 warps (4 along m, 2 along n).
// smem layout (bytes):
//   qfrag  float4[2048]  : 0      .. 32768    A-fragments of Q (4 mt x 16 ks)
//   kvfrag float2[4096]  : 32768  .. 65536    B-fragments of K (8 nt x 16 ks) / V (16 nt x 8 ks)
//   pfrag  float4[1024]  : 65536  .. 81920    A-fragments of P (4 mt x 8 ks)
//   Ps     float[64*68]  : 81920  .. 99328    raw masked logits
//   smM/L/F float[64]x3  : 99328  .. 100096
#define ATTN_SMEM_BYTES 100096

__global__ void __launch_bounds__(256) attn_kernel() {
    extern __shared__ char smraw[];
    float4* qfrag  = (float4*)smraw;
    float2* kvfrag = (float2*)(smraw + 32768);
    float4* pfrag  = (float4*)(smraw + 65536);
    float*  Ps     = (float*)(smraw + 81920);
    float*  smM    = (float*)(smraw + 99328);
    float*  smL    = smM + 64;
    float*  smF    = smL + 64;

    const int tid  = threadIdx.x;
    const int lane = tid & 31;
    const int wid  = tid >> 5;
    const int wm   = wid & 3;    // m-tile 0..3 (16 rows each)
    const int wn   = wid >> 2;   // n half 0..1

    const int qb  = blockIdx.x;
    const int h   = blockIdx.y;
    const int b   = blockIdx.z;
    const int q0  = qb << 6;
    const int kvh = h >> 2;

    const float* Qg = g_Q + (size_t)(b * L_ + q0) * D_ + h * DK_;
    const float* Kg = g_K + (size_t)(b * L_) * DKV_ + kvh * DK_;
    const float* Vg = g_V + (size_t)(b * L_) * DKV_ + kvh * DK_;

    // ---- load Q into A-fragment layout (tf32) ----
    #pragma unroll
    for (int it = 0; it < 8; it++) {
        int idx = tid + (it << 8);       // 0..2047
        int row = idx >> 5;              // q row 0..63
        int c4  = idx & 31;              // float4 along dim
        float4 v = *(const float4*)(Qg + (size_t)row * D_ + (c4 << 2));
        int ks = c4 >> 1, half = c4 & 1;
        int mq = row >> 4, rr = row & 15, g = rr & 7, hi = rr >> 3;
        float* dst = (float*)&qfrag[((mq * 16 + ks) << 5) + (g << 2)] + (half << 1) + hi;
        dst[0]  = to_tf32(v.x);
        dst[4]  = to_tf32(v.y);
        dst[8]  = to_tf32(v.z);
        dst[12] = to_tf32(v.w);
    }
    if (tid < 64) { smM[tid] = -1e30f; smL[tid] = 0.0f; }

    float o[8][4];                       // PV accum: warp tile m16 x n64 (8 n-tiles)
    #pragma unroll
    for (int j = 0; j < 8; j++)
        #pragma unroll
        for (int r = 0; r < 4; r++) o[j][r] = 0.0f;

    const float scale = 0.08838834764831845f;  // 1/sqrt(128)
    const int nkb = qb + 1;

    for (int kb = 0; kb < nkb; kb++) {
        const int k0 = kb << 6;
        __syncthreads();   // prior PV reads of kvfrag/pfrag complete

        // ---- load K tile into B-fragment layout (n=kv, k=dim) ----
        #pragma unroll
        for (int it = 0; it < 8; it++) {
            int idx = tid + (it << 8);
            int row = idx >> 5;          // kv 0..63
            int c4  = idx & 31;
            float4 v = *(const float4*)(Kg + (size_t)(k0 + row) * DKV_ + (c4 << 2));
            int ks = c4 >> 1, half = c4 & 1;
            int nq = row >> 3, g = row & 7;
            float* dst = (float*)&kvfrag[((nq * 16 + ks) << 5) + (g << 2)] + half;
            dst[0] = to_tf32(v.x);
            dst[2] = to_tf32(v.y);
            dst[4] = to_tf32(v.z);
            dst[6] = to_tf32(v.w);
        }
        __syncthreads();

        // ---- S = Q K^T via mma; write scaled+masked logits to Ps ----
        {
            float s[4][4];
            #pragma unroll
            for (int j = 0; j < 4; j++)
                #pragma unroll
                for (int r = 0; r < 4; r++) s[j][r] = 0.0f;

            #pragma unroll
            for (int ks = 0; ks < 16; ks++) {
                float4 a = qfrag[((wm * 16 + ks) << 5) + lane];
                #pragma unroll
                for (int j = 0; j < 4; j++) {
                    float2 bfr = kvfrag[(((wn * 4 + j) * 16 + ks) << 5) + lane];
                    mma_tf32(s[j], a, bfr);
                }
            }

            int r0 = wm * 16 + (lane >> 2);
            int r1 = r0 + 8;
            #pragma unroll
            for (int j = 0; j < 4; j++) {
                int c0 = (wn * 4 + j) * 8 + ((lane & 3) << 1);
                float v00 = s[j][0] * scale, v01 = s[j][1] * scale;
                float v10 = s[j][2] * scale, v11 = s[j][3] * scale;
                if (k0 + c0     > q0 + r0) v00 = -1e30f;
                if (k0 + c0 + 1 > q0 + r0) v01 = -1e30f;
                if (k0 + c0     > q0 + r1) v10 = -1e30f;
                if (k0 + c0 + 1 > q0 + r1) v11 = -1e30f;
                *(float2*)&Ps[r0 * 68 + c0] = make_float2(v00, v01);
                *(float2*)&Ps[r1 * 68 + c0] = make_float2(v10, v11);
            }
        }
        __syncthreads();   // Ps visible; K reads done -> kv buffer reusable for V

        // ---- load V tile into B-fragment layout (n=dim, k=kv) ----
        #pragma unroll
        for (int it = 0; it < 8; it++) {
            int idx = tid + (it << 8);
            int row = idx >> 5;          // kv 0..63
            int c4  = idx & 31;
            float4 v = *(const float4*)(Vg + (size_t)(k0 + row) * DKV_ + (c4 << 2));
            int ksv  = row >> 3;
            int comp = (row >> 2) & 1;
            int lbase = row & 3;
            float vv[4] = {v.x, v.y, v.z, v.w};
            #pragma unroll
            for (int j = 0; j < 4; j++) {
                int n  = (c4 << 2) + j;
                int nt = n >> 3;
                int ln = ((n & 7) << 2) + lbase;
                float* dst = (float*)&kvfrag[((nt * 8 + ksv) << 5) + ln] + comp;
                *dst = to_tf32(vv[j]);
            }
        }

        // ---- online softmax: 4 threads per row ----
        {
            int r   = tid >> 2;
            int seg = tid & 3;
            float v[16];
            #pragma unroll
            for (int q = 0; q < 4; q++) {
                float4 t = *(float4*)&Ps[r * 68 + seg * 16 + q * 4];
                v[q * 4 + 0] = t.x; v[q * 4 + 1] = t.y;
                v[q * 4 + 2] = t.z; v[q * 4 + 3] = t.w;
            }
            float mx = v[0];
            #pragma unroll
            for (int q = 1; q < 16; q++) mx = fmaxf(mx, v[q]);
            mx = fmaxf(mx, __shfl_xor_sync(0xffffffffu, mx, 1));
            mx = fmaxf(mx, __shfl_xor_sync(0xffffffffu, mx, 2));
            float m_old = smM[r];
            float m_new = fmaxf(m_old, mx);
            float sum = 0.0f;
            #pragma unroll
            for (int q = 0; q < 16; q++) {
                v[q] = __expf(v[q] - m_new);
                sum += v[q];
            }
            sum += __shfl_xor_sync(0xffffffffu, sum, 1);
            sum += __shfl_xor_sync(0xffffffffu, sum, 2);
            float fac = __expf(m_old - m_new);
            if (seg == 0) {
                smM[r] = m_new;
                smL[r] = smL[r] * fac + sum;
                smF[r] = fac;
            }
            // write P into A-fragment layout (tf32)
            int mt = r >> 4, rr = r & 15;
            int gl = rr & 7, hi = rr >> 3;
            #pragma unroll
            for (int q = 0; q < 16; q++) {
                int c  = seg * 16 + q;
                int ks = c >> 3;
                int ln = (gl << 2) + (c & 3);
                int comp = (((c >> 2) & 1) << 1) + hi;
                float* dst = (float*)&pfrag[((mt * 8 + ks) << 5) + ln] + comp;
                *dst = to_tf32(v[q]);
            }
        }
        __syncthreads();   // vfrag + pfrag + smF ready

        // ---- rescale O accum, then O += P V via mma ----
        {
            int r0 = wm * 16 + (lane >> 2);
            float f0 = smF[r0];
            float f1 = smF[r0 + 8];
            #pragma unroll
            for (int j = 0; j < 8; j++) {
                o[j][0] *= f0; o[j][1] *= f0;
                o[j][2] *= f1; o[j][3] *= f1;
            }
            #pragma unroll
            for (int ks = 0; ks < 8; ks++) {
                float4 a = pfrag[((wm * 8 + ks) << 5) + lane];
                #pragma unroll
                for (int j = 0; j < 8; j++) {
                    float2 bfr = kvfrag[(((wn * 8 + j) * 8 + ks) << 5) + lane];
                    mma_tf32(o[j], a, bfr);
                }
            }
        }
    }

    // ---- epilogue: normalize, write g_O ----
    {
        int r0 = wm * 16 + (lane >> 2);
        int r1 = r0 + 8;
        float inv0 = 1.0f / smL[r0];
        float inv1 = 1.0f / smL[r1];
        float* op0 = g_O + (size_t)(b * L_ + q0 + r0) * D_ + h * DK_;
        float* op1 = g_O + (size_t)(b * L_ + q0 + r1) * D_ + h * DK_;
        #pragma unroll
        for (int j = 0; j < 8; j++) {
            int n = (wn * 8 + j) * 8 + ((lane & 3) << 1);
            *(float2*)(op0 + n) = make_float2(o[j][0] * inv0, o[j][1] * inv0);
            *(float2*)(op1 + n) = make_float2(o[j][2] * inv1, o[j][3] * inv1);
        }
    }
}

// ---------------- launch ----------------
extern "C" void kernel_launch(void* const* d_in, const int* in_sizes, int n_in,
                              void* d_out, int out_size) {
    const float* query = (const float*)d_in[0];
    const float* key_t = (const float*)d_in[1];
    const float* value = (const float*)d_in[2];
    // d_in[3] = mask (causal tril; unused)
    const float* Wq = (const float*)d_in[4];
    const float* Wk = (const float*)d_in[5];
    const float* Wv = (const float*)d_in[6];
    const float* Wo = (const float*)d_in[7];
    float* out = (float*)d_out;

    float *Qb, *Kb, *Vb, *Ob;
    cudaGetSymbolAddress((void**)&Qb, g_Q);
    cudaGetSymbolAddress((void**)&Kb, g_K);
    cudaGetSymbolAddress((void**)&Vb, g_V);
    cudaGetSymbolAddress((void**)&Ob, g_O);

    cudaFuncSetAttribute(gemm_tf32_kernel, cudaFuncAttributeMaxDynamicSharedMemorySize,
                         GEMM_SMEM_BYTES);
    cudaFuncSetAttribute(attn_kernel, cudaFuncAttributeMaxDynamicSharedMemorySize,
                         ATTN_SMEM_BYTES);

    rope_table_kernel<<<512, 256>>>();

    gemm_tf32_kernel<<<dim3(D_ / 128, M_ / 128), 256, GEMM_SMEM_BYTES>>>(query, Wq, Qb, M_, D_, D_);
    gemm_tf32_kernel<<<dim3(DKV_ / 128, M_ / 128), 256, GEMM_SMEM_BYTES>>>(key_t, Wk, Kb, M_, DKV_, D_);
    gemm_tf32_kernel<<<dim3(DKV_ / 128, M_ / 128), 256, GEMM_SMEM_BYTES>>>(value, Wv, Vb, M_, DKV_, D_);

    rope_apply_kernel<<<(M_ * H_ * 64) / 256, 256>>>(Qb, H_, D_);
    rope_apply_kernel<<<(M_ * KVH_ * 64) / 256, 256>>>(Kb, KVH_, DKV_);

    attn_kernel<<<dim3(L_ / 64, H_, B_), 256, ATTN_SMEM_BYTES>>>();

    gemm_tf32_kernel<<<dim3(D_ / 128, M_ / 128), 256, GEMM_SMEM_BYTES>>>(Ob, Wo, out, M_, D_, D_);
}

// round 5
// speedup vs baseline: 2.0699x; 2.0699x over previous
#include <cuda_runtime.h>
#include <cuda_bf16.h>
#include <math.h>

// Problem constants
#define B_    2
#define L_    2048
#define D_    2048
#define H_    16
#define KVH_  4
#define DK_   128
#define DKV_  512            // KVH_ * DK_
#define M_    (B_ * L_)      // 4096 rows
#define CAPV  50.0f

// ---------------- scratch (static device globals; no allocation) ----------------
static __device__ float g_Q[(size_t)M_ * D_];
static __device__ float g_K[(size_t)M_ * DKV_];
static __device__ float g_V[(size_t)M_ * DKV_];
static __device__ float g_O[(size_t)M_ * D_];
static __device__ float g_cos[L_ * 64];
static __device__ float g_sin[L_ * 64];

// ---------------- RoPE table ----------------
__global__ void rope_table_kernel() {
    int idx = blockIdx.x * blockDim.x + threadIdx.x;
    if (idx >= L_ * 64) return;
    int pos = idx >> 6;
    int i   = idx & 63;
    float expnt = (float)(2 * i) / 128.0f;
    float invf  = powf(10000.0f, -expnt);
    float f     = (float)pos * invf;
    g_cos[idx] = cosf(f);
    g_sin[idx] = sinf(f);
}

// ---------------- RoPE apply + clip (in place) ----------------
__global__ void rope_apply_kernel(float* __restrict__ X, int heads, int rowstride) {
    int idx   = blockIdx.x * blockDim.x + threadIdx.x;
    int total = M_ * heads * 64;
    if (idx >= total) return;
    int i   = idx & 63;
    int t   = idx >> 6;
    int h   = t % heads;
    int row = t / heads;
    int pos = row & (L_ - 1);
    float c = g_cos[(pos << 6) + i];
    float s = g_sin[(pos << 6) + i];
    float* p = X + (size_t)row * rowstride + h * DK_ + i;
    float x1 = p[0], x2 = p[64];
    float o1 = x1 * c - x2 * s;
    float o2 = x1 * s + x2 * c;
    p[0]  = fminf(fmaxf(o1, -CAPV), CAPV);
    p[64] = fminf(fmaxf(o2, -CAPV), CAPV);
}

// ---------------- tf32 helpers ----------------
__device__ __forceinline__ float to_tf32(float x) {
    float r;
    asm("cvt.rna.tf32.f32 %0, %1;" : "=f"(r) : "f"(x));
    return r;
}

__device__ __forceinline__ float4 to_tf32_4(float4 v) {
    return make_float4(to_tf32(v.x), to_tf32(v.y), to_tf32(v.z), to_tf32(v.w));
}

__device__ __forceinline__ void mma_tf32(float* c, const float4& a, const float2& b) {
    const unsigned* A  = reinterpret_cast<const unsigned*>(&a);
    const unsigned* Bv = reinterpret_cast<const unsigned*>(&b);
    asm volatile(
        "mma.sync.aligned.m16n8k8.row.col.f32.tf32.tf32.f32 "
        "{%0,%1,%2,%3}, {%4,%5,%6,%7}, {%8,%9}, {%0,%1,%2,%3};"
        : "+f"(c[0]), "+f"(c[1]), "+f"(c[2]), "+f"(c[3])
        : "r"(A[0]), "r"(A[1]), "r"(A[2]), "r"(A[3]), "r"(Bv[0]), "r"(Bv[1]));
}

// ---------------- tf32 NT GEMM, double-buffered, row-major pitch-36 smem --------
// C[M,N] = A[M,K] * Bw[N,K]^T.  BM=BN=128, BK=32, 256 threads (8 warps 2x4).
// Tiles stored row-major, pitch 36 floats (36 mod 32 = 4 -> natural bank swizzle).
// Stores: STS.128 conflict-free. Fragment gathers: LDS.32, banks 4*(lane>>2)+(lane&3),
// all 32 distinct -> conflict-free.
#define GEMM_TILE_F   (128 * 36)                 // floats per tile
#define GEMM_SMEM_BYTES (2 * 2 * GEMM_TILE_F * 4)  // 2 stages * (A+B) = 73728

__global__ void __launch_bounds__(256) gemm_tf32_kernel(
    const float* __restrict__ A, const float* __restrict__ Bw,
    float* __restrict__ C, int M, int N, int K)
{
    extern __shared__ float smg[];
    float* sA = smg;                       // [2][128*36]
    float* sB = smg + 2 * GEMM_TILE_F;     // [2][128*36]

    const int tid    = threadIdx.x;
    const int lane   = tid & 31;
    const int wid    = tid >> 5;
    const int warp_m = wid & 1;
    const int warp_n = wid >> 1;
    const int bm     = blockIdx.y << 7;
    const int bn     = blockIdx.x << 7;

    float acc[4][4][4];
    #pragma unroll
    for (int mt = 0; mt < 4; mt++)
        #pragma unroll
        for (int nt = 0; nt < 4; nt++)
            #pragma unroll
            for (int r = 0; r < 4; r++) acc[mt][nt][r] = 0.0f;

    float4 avA[4], avB[4];
    #pragma unroll
    for (int i = 0; i < 4; i++) {
        int idx = tid + (i << 8);          // 0..1023
        int row = idx >> 3;
        int c4  = idx & 7;
        avA[i] = *(const float4*)(A  + (size_t)(bm + row) * K + (c4 << 2));
        avB[i] = *(const float4*)(Bw + (size_t)(bn + row) * K + (c4 << 2));
    }

    auto store_stage = [&](int s) {
        float* dA = sA + s * GEMM_TILE_F;
        float* dB = sB + s * GEMM_TILE_F;
        #pragma unroll
        for (int i = 0; i < 4; i++) {
            int idx = tid + (i << 8);
            int row = idx >> 3;
            int c4  = idx & 7;
            *(float4*)&dA[row * 36 + (c4 << 2)] = to_tf32_4(avA[i]);
            *(float4*)&dB[row * 36 + (c4 << 2)] = to_tf32_4(avB[i]);
        }
    };

    store_stage(0);
    __syncthreads();

    const int m   = lane & 3;
    const int rr  = lane >> 2;
    const int stages = K >> 5;

    for (int kt = 0; kt < stages; kt++) {
        const int s = kt & 1;
        const bool has_next = (kt + 1) < stages;
        if (has_next) {
            int koff = (kt + 1) << 5;
            #pragma unroll
            for (int i = 0; i < 4; i++) {
                int idx = tid + (i << 8);
                int row = idx >> 3;
                int c4  = idx & 7;
                avA[i] = *(const float4*)(A  + (size_t)(bm + row) * K + koff + (c4 << 2));
                avB[i] = *(const float4*)(Bw + (size_t)(bn + row) * K + koff + (c4 << 2));
            }
        }

        const float* rA = sA + s * GEMM_TILE_F + (warp_m * 64 + rr) * 36;
        const float* rB = sB + s * GEMM_TILE_F + (warp_n * 32 + rr) * 36;
        #pragma unroll
        for (int ks = 0; ks < 4; ks++) {
            const int c = (ks << 3) + m;
            float4 a[4];
            float2 b[4];
            #pragma unroll
            for (int mt = 0; mt < 4; mt++) {
                const float* p = rA + mt * 16 * 36 + c;
                a[mt] = make_float4(p[0], p[8 * 36], p[4], p[8 * 36 + 4]);
            }
            #pragma unroll
            for (int nt = 0; nt < 4; nt++) {
                const float* p = rB + nt * 8 * 36 + c;
                b[nt] = make_float2(p[0], p[4]);
            }
            #pragma unroll
            for (int mt = 0; mt < 4; mt++)
                #pragma unroll
                for (int nt = 0; nt < 4; nt++)
                    mma_tf32(acc[mt][nt], a[mt], b[nt]);
        }

        if (has_next) store_stage(s ^ 1);
        __syncthreads();
    }

    const int g   = lane >> 2;
    const int tig = lane & 3;
    #pragma unroll
    for (int mt = 0; mt < 4; mt++) {
        int r0 = bm + warp_m * 64 + mt * 16 + g;
        #pragma unroll
        for (int nt = 0; nt < 4; nt++) {
            int c = bn + warp_n * 32 + nt * 8 + (tig << 1);
            *(float2*)(&C[(size_t)r0 * N + c])       = make_float2(acc[mt][nt][0], acc[mt][nt][1]);
            *(float2*)(&C[(size_t)(r0 + 8) * N + c]) = make_float2(acc[mt][nt][2], acc[mt][nt][3]);
        }
    }
}

// ---------------- tf32 tensor-core flash attention (causal) ----------------
// CTA: 64 q-rows x 64 kv tile, DK=128. 256 threads, 8 warps (4 m-tiles x 2 n-halves).
// Row-major smem with swizzling pitches:
//   Qs  float[64*132]  pitch 132 (=4 mod 32)   @ 0
//   KVs float[64*136]  K uses pitch 132, V 136 @ 33792 B
//   Ps  float[64*68]   pitch 68  (=4 mod 32)   @ 68608 B
//   smM/L/F float[64]                          @ 86016 B
#define ATTN_SMEM_BYTES 86784

__global__ void __launch_bounds__(256, 2) attn_kernel() {
    extern __shared__ float smf[];
    float* Qs  = smf;             // 8448 floats
    float* KVs = smf + 8448;      // 8704 floats
    float* Ps  = smf + 17152;     // 4352 floats
    float* smM = smf + 21504;
    float* smL = smM + 64;
    float* smF = smL + 64;

    const int tid  = threadIdx.x;
    const int lane = tid & 31;
    const int wid  = tid >> 5;
    const int wm   = wid & 3;    // m-tile 0..3 (16 rows each)
    const int wn   = wid >> 2;   // n half 0..1
    const int m_   = lane & 3;
    const int rr   = lane >> 2;

    const int qb  = blockIdx.x;
    const int h   = blockIdx.y;
    const int b   = blockIdx.z;
    const int q0  = qb << 6;
    const int kvh = h >> 2;

    const float* Qg = g_Q + (size_t)(b * L_ + q0) * D_ + h * DK_;
    const float* Kg = g_K + (size_t)(b * L_) * DKV_ + kvh * DK_;
    const float* Vg = g_V + (size_t)(b * L_) * DKV_ + kvh * DK_;

    // ---- load Q row-major, pitch 132, tf32 ----
    #pragma unroll
    for (int it = 0; it < 8; it++) {
        int idx = tid + (it << 8);       // 0..2047
        int row = idx >> 5;
        int c4  = idx & 31;
        float4 v = *(const float4*)(Qg + (size_t)row * D_ + (c4 << 2));
        *(float4*)&Qs[row * 132 + (c4 << 2)] = to_tf32_4(v);
    }
    if (tid < 64) { smM[tid] = -1e30f; smL[tid] = 0.0f; }

    float o[8][4];
    #pragma unroll
    for (int j = 0; j < 8; j++)
        #pragma unroll
        for (int r = 0; r < 4; r++) o[j][r] = 0.0f;

    const float scale = 0.08838834764831845f;  // 1/sqrt(128)
    const int nkb = qb + 1;

    for (int kb = 0; kb < nkb; kb++) {
        const int k0 = kb << 6;
        __syncthreads();   // prior PV reads of KVs/Ps complete; Q ready (iter 0)

        // ---- K tile row-major, pitch 132, tf32 ----
        #pragma unroll
        for (int it = 0; it < 8; it++) {
            int idx = tid + (it << 8);
            int row = idx >> 5;
            int c4  = idx & 31;
            float4 v = *(const float4*)(Kg + (size_t)(k0 + row) * DKV_ + (c4 << 2));
            *(float4*)&KVs[row * 132 + (c4 << 2)] = to_tf32_4(v);
        }
        __syncthreads();

        // ---- S = Q K^T via mma ----
        {
            float s4[4][4];
            #pragma unroll
            for (int j = 0; j < 4; j++)
                #pragma unroll
                for (int r = 0; r < 4; r++) s4[j][r] = 0.0f;

            const float* qbase = &Qs[(wm * 16 + rr) * 132];
            const float* kbase = &KVs[(wn * 32 + rr) * 132];
            #pragma unroll
            for (int ks = 0; ks < 16; ks++) {
                const int c = (ks << 3) + m_;
                const float* qp = qbase + c;
                float4 a = make_float4(qp[0], qp[8 * 132], qp[4], qp[8 * 132 + 4]);
                #pragma unroll
                for (int j = 0; j < 4; j++) {
                    const float* kp = kbase + j * 8 * 132 + c;
                    float2 bfr = make_float2(kp[0], kp[4]);
                    mma_tf32(s4[j], a, bfr);
                }
            }

            int r0 = wm * 16 + rr;
            int r1 = r0 + 8;
            #pragma unroll
            for (int j = 0; j < 4; j++) {
                int c0 = (wn * 4 + j) * 8 + (m_ << 1);
                float v00 = s4[j][0] * scale, v01 = s4[j][1] * scale;
                float v10 = s4[j][2] * scale, v11 = s4[j][3] * scale;
                if (k0 + c0     > q0 + r0) v00 = -1e30f;
                if (k0 + c0 + 1 > q0 + r0) v01 = -1e30f;
                if (k0 + c0     > q0 + r1) v10 = -1e30f;
                if (k0 + c0 + 1 > q0 + r1) v11 = -1e30f;
                *(float2*)&Ps[r0 * 68 + c0] = make_float2(v00, v01);
                *(float2*)&Ps[r1 * 68 + c0] = make_float2(v10, v11);
            }
        }
        __syncthreads();   // Ps written; K reads done -> KVs reusable for V

        // ---- V tile row-major, pitch 136, tf32 (overwrites K buffer) ----
        #pragma unroll
        for (int it = 0; it < 8; it++) {
            int idx = tid + (it << 8);
            int row = idx >> 5;
            int c4  = idx & 31;
            float4 v = *(const float4*)(Vg + (size_t)(k0 + row) * DKV_ + (c4 << 2));
            *(float4*)&KVs[row * 136 + (c4 << 2)] = to_tf32_4(v);
        }

        // ---- online softmax: 4 threads per row; exp written back to Ps (tf32) ----
        {
            int r   = tid >> 2;
            int seg = tid & 3;
            float v[16];
            #pragma unroll
            for (int q = 0; q < 4; q++) {
                float4 t = *(float4*)&Ps[r * 68 + seg * 16 + (q << 2)];
                v[q * 4 + 0] = t.x; v[q * 4 + 1] = t.y;
                v[q * 4 + 2] = t.z; v[q * 4 + 3] = t.w;
            }
            float mx = v[0];
            #pragma unroll
            for (int q = 1; q < 16; q++) mx = fmaxf(mx, v[q]);
            mx = fmaxf(mx, __shfl_xor_sync(0xffffffffu, mx, 1));
            mx = fmaxf(mx, __shfl_xor_sync(0xffffffffu, mx, 2));
            float m_old = smM[r];
            float m_new = fmaxf(m_old, mx);
            float sum = 0.0f;
            #pragma unroll
            for (int q = 0; q < 16; q++) {
                v[q] = __expf(v[q] - m_new);
                sum += v[q];
            }
            sum += __shfl_xor_sync(0xffffffffu, sum, 1);
            sum += __shfl_xor_sync(0xffffffffu, sum, 2);
            float fac = __expf(m_old - m_new);
            if (seg == 0) {
                smM[r] = m_new;
                smL[r] = smL[r] * fac + sum;
                smF[r] = fac;
            }
            #pragma unroll
            for (int q = 0; q < 4; q++) {
                float4 t = make_float4(to_tf32(v[q * 4 + 0]), to_tf32(v[q * 4 + 1]),
                                       to_tf32(v[q * 4 + 2]), to_tf32(v[q * 4 + 3]));
                *(float4*)&Ps[r * 68 + seg * 16 + (q << 2)] = t;
            }
        }
        __syncthreads();   // V + exp(P) + smF ready

        // ---- rescale O accum, then O += P V via mma ----
        {
            int r0 = wm * 16 + rr;
            float f0 = smF[r0];
            float f1 = smF[r0 + 8];
            #pragma unroll
            for (int j = 0; j < 8; j++) {
                o[j][0] *= f0; o[j][1] *= f0;
                o[j][2] *= f1; o[j][3] *= f1;
            }
            const float* pbase = &Ps[(wm * 16 + rr) * 68];
            #pragma unroll
            for (int ks = 0; ks < 8; ks++) {
                const int c = (ks << 3) + m_;
                const float* pp = pbase + c;
                float4 a = make_float4(pp[0], pp[8 * 68], pp[4], pp[8 * 68 + 4]);
                const float* vbase = &KVs[c * 136 + wn * 64 + rr];
                #pragma unroll
                for (int j = 0; j < 8; j++) {
                    const float* vp = vbase + (j << 3);
                    float2 bfr = make_float2(vp[0], vp[4 * 136]);
                    mma_tf32(o[j], a, bfr);
                }
            }
        }
    }

    // ---- epilogue: normalize, write g_O ----
    {
        int r0 = wm * 16 + rr;
        int r1 = r0 + 8;
        float inv0 = 1.0f / smL[r0];
        float inv1 = 1.0f / smL[r1];
        float* op0 = g_O + (size_t)(b * L_ + q0 + r0) * D_ + h * DK_;
        float* op1 = g_O + (size_t)(b * L_ + q0 + r1) * D_ + h * DK_;
        #pragma unroll
        for (int j = 0; j < 8; j++) {
            int n = (wn * 8 + j) * 8 + (m_ << 1);
            *(float2*)(op0 + n) = make_float2(o[j][0] * inv0, o[j][1] * inv0);
            *(float2*)(op1 + n) = make_float2(o[j][2] * inv1, o[j][3] * inv1);
        }
    }
}

// ---------------- launch ----------------
extern "C" void kernel_launch(void* const* d_in, const int* in_sizes, int n_in,
                              void* d_out, int out_size) {
    const float* query = (const float*)d_in[0];
    const float* key_t = (const float*)d_in[1];
    const float* value = (const float*)d_in[2];
    // d_in[3] = mask (causal tril; unused)
    const float* Wq = (const float*)d_in[4];
    const float* Wk = (const float*)d_in[5];
    const float* Wv = (const float*)d_in[6];
    const float* Wo = (const float*)d_in[7];
    float* out = (float*)d_out;

    float *Qb, *Kb, *Vb, *Ob;
    cudaGetSymbolAddress((void**)&Qb, g_Q);
    cudaGetSymbolAddress((void**)&Kb, g_K);
    cudaGetSymbolAddress((void**)&Vb, g_V);
    cudaGetSymbolAddress((void**)&Ob, g_O);

    cudaFuncSetAttribute(gemm_tf32_kernel, cudaFuncAttributeMaxDynamicSharedMemorySize,
                         GEMM_SMEM_BYTES);
    cudaFuncSetAttribute(attn_kernel, cudaFuncAttributeMaxDynamicSharedMemorySize,
                         ATTN_SMEM_BYTES);

    rope_table_kernel<<<512, 256>>>();

    gemm_tf32_kernel<<<dim3(D_ / 128, M_ / 128), 256, GEMM_SMEM_BYTES>>>(query, Wq, Qb, M_, D_, D_);
    gemm_tf32_kernel<<<dim3(DKV_ / 128, M_ / 128), 256, GEMM_SMEM_BYTES>>>(key_t, Wk, Kb, M_, DKV_, D_);
    gemm_tf32_kernel<<<dim3(DKV_ / 128, M_ / 128), 256, GEMM_SMEM_BYTES>>>(value, Wv, Vb, M_, DKV_, D_);

    rope_apply_kernel<<<(M_ * H_ * 64) / 256, 256>>>(Qb, H_, D_);
    rope_apply_kernel<<<(M_ * KVH_ * 64) / 256, 256>>>(Kb, KVH_, DKV_);

    attn_kernel<<<dim3(L_ / 64, H_, B_), 256, ATTN_SMEM_BYTES>>>();

    gemm_tf32_kernel<<<dim3(D_ / 128, M_ / 128), 256, GEMM_SMEM_BYTES>>>(Ob, Wo, out, M_, D_, D_);
}